// round 1
// baseline (speedup 1.0000x reference)
#include <cuda_runtime.h>
#include <cuda_bf16.h>
#include <cstdint>

// Problem constants (fixed by reference setup_inputs)
#define Bq     4
#define NPIX   4096          // 64*64
#define HMAPC  64
#define WMAPC  64
#define HEADS  8
#define HD     64
#define DIMM   512
#define INNER  512           // HEADS*HD
#define MROWS  (Bq*NPIX)     // 16384
#define QKV_N  (3*INNER)     // 1536

// Scratch (device globals — no runtime allocation allowed)
__device__ float g_qkv[(size_t)MROWS * QKV_N];   // ~100.7 MB
__device__ float g_att[(size_t)MROWS * INNER];   // ~33.5 MB

// ---------------------------------------------------------------------------
// Packed fp32x2 helpers (sm_103a FFMA2 — only reachable via PTX fma.rn.f32x2)
// ---------------------------------------------------------------------------
__device__ __forceinline__ unsigned long long fma_f32x2(unsigned long long a,
                                                        unsigned long long b,
                                                        unsigned long long c) {
    unsigned long long d;
    asm("fma.rn.f32x2 %0, %1, %2, %3;" : "=l"(d) : "l"(a), "l"(b), "l"(c));
    return d;
}
__device__ __forceinline__ unsigned long long pack2(float x) {
    unsigned long long r;
    asm("mov.b64 %0, {%1, %1};" : "=l"(r) : "f"(x));
    return r;
}

// ---------------------------------------------------------------------------
// GEMM: C[M,N] = A[M,K] @ B[N,K]^T (+ bias[N]).  Both operands K-major.
// 128x128x16 tile, 256 threads, 8x8 microtile, FFMA2 inner loop.
// Requires M%128==0, N%128==0, K%16==0 (true for all calls here).
// ---------------------------------------------------------------------------
#define BM  128
#define BN  128
#define BKK 16
#define TM  8
#define TN  8

__global__ void __launch_bounds__(256)
gemm_tn(const float* __restrict__ A, const float* __restrict__ B,
        const float* __restrict__ bias, float* __restrict__ C,
        int M, int N, int K)
{
    __shared__ float As[BKK][BM];
    __shared__ float Bs[BKK][BN];

    const int tid = threadIdx.x;
    const int tx  = tid & 15;      // N direction, 0..15
    const int ty  = tid >> 4;      // M direction, 0..15
    const int bm  = blockIdx.y * BM;
    const int bn  = blockIdx.x * BN;

    const int lrow = tid >> 2;        // 0..63
    const int lc4  = (tid & 3) * 4;   // 0,4,8,12

    unsigned long long acc[TM][TN/2];
#pragma unroll
    for (int i = 0; i < TM; i++)
#pragma unroll
        for (int j = 0; j < TN/2; j++) acc[i][j] = 0ull;

    for (int k0 = 0; k0 < K; k0 += BKK) {
#pragma unroll
        for (int p = 0; p < 2; p++) {
            const int row = lrow + p * 64;
            float4 va = *reinterpret_cast<const float4*>(
                &A[(size_t)(bm + row) * K + k0 + lc4]);
            As[lc4 + 0][row] = va.x;
            As[lc4 + 1][row] = va.y;
            As[lc4 + 2][row] = va.z;
            As[lc4 + 3][row] = va.w;
            float4 vb = *reinterpret_cast<const float4*>(
                &B[(size_t)(bn + row) * K + k0 + lc4]);
            Bs[lc4 + 0][row] = vb.x;
            Bs[lc4 + 1][row] = vb.y;
            Bs[lc4 + 2][row] = vb.z;
            Bs[lc4 + 3][row] = vb.w;
        }
        __syncthreads();

#pragma unroll
        for (int kk = 0; kk < BKK; kk++) {
            float4 a0 = *reinterpret_cast<const float4*>(&As[kk][ty * TM]);
            float4 a1 = *reinterpret_cast<const float4*>(&As[kk][ty * TM + 4]);
            const unsigned long long* bp =
                reinterpret_cast<const unsigned long long*>(&Bs[kk][tx * TN]);
            unsigned long long bb[4];
#pragma unroll
            for (int j = 0; j < 4; j++) bb[j] = bp[j];
            float av[8] = {a0.x, a0.y, a0.z, a0.w, a1.x, a1.y, a1.z, a1.w};
#pragma unroll
            for (int i = 0; i < TM; i++) {
                unsigned long long a2 = pack2(av[i]);
#pragma unroll
                for (int j = 0; j < 4; j++)
                    acc[i][j] = fma_f32x2(a2, bb[j], acc[i][j]);
            }
        }
        __syncthreads();
    }

    // Epilogue
#pragma unroll
    for (int i = 0; i < TM; i++) {
        const int row = bm + ty * TM + i;
        float* cp = &C[(size_t)row * N + bn + tx * TN];
#pragma unroll
        for (int j = 0; j < 4; j++) {
            float lo = __uint_as_float((unsigned)(acc[i][j] & 0xffffffffull));
            float hi = __uint_as_float((unsigned)(acc[i][j] >> 32));
            const int n0 = bn + tx * TN + j * 2;
            if (bias) { lo += bias[n0]; hi += bias[n0 + 1]; }
            float2 v2 = make_float2(lo, hi);
            *reinterpret_cast<float2*>(&cp[j * 2]) = v2;
        }
    }
}

// ---------------------------------------------------------------------------
// Local 5x5 attention. One warp per (b, head, pixel).
// qkv layout: [b*NPIX, 1536] with q at [0,512), k at [512,1024), v at [1024,1536),
// head h occupying h*64..h*64+63 inside each 512-block.
// OOB neighbors: k zero-padded -> dot = 0 (participates in softmax), v = 0.
// ---------------------------------------------------------------------------
__global__ void __launch_bounds__(256)
local_attn(const float* __restrict__ qkv, float* __restrict__ out)
{
    const int warp = (blockIdx.x << 3) + (threadIdx.x >> 5);
    const int lane = threadIdx.x & 31;

    const int pix  = warp & (NPIX - 1);
    const int bh   = warp >> 12;
    const int head = bh & (HEADS - 1);
    const int b    = bh >> 3;
    const int y    = pix >> 6;
    const int x    = pix & 63;

    const float* base = qkv + (size_t)b * NPIX * QKV_N;
    const float* qp   = base + (size_t)pix * QKV_N + head * HD;
    const float q0 = qp[lane];
    const float q1 = qp[lane + 32];

    float dots[25];
#pragma unroll
    for (int f = 0; f < 25; f++) {
        const int ny = y + f / 5 - 2;
        const int nx = x + f % 5 - 2;
        float d = 0.f;
        if ((unsigned)ny < (unsigned)HMAPC && (unsigned)nx < (unsigned)WMAPC) {
            const float* kp = base + (size_t)((ny << 6) + nx) * QKV_N
                              + INNER + head * HD;
            d = q0 * kp[lane] + q1 * kp[lane + 32];
        }
#pragma unroll
        for (int o = 16; o > 0; o >>= 1)
            d += __shfl_xor_sync(0xffffffffu, d, o);
        dots[f] = d * 0.125f;   // 64^-0.5
    }

    float m = dots[0];
#pragma unroll
    for (int f = 1; f < 25; f++) m = fmaxf(m, dots[f]);
    float s = 0.f;
#pragma unroll
    for (int f = 0; f < 25; f++) { dots[f] = __expf(dots[f] - m); s += dots[f]; }
    const float inv = 1.0f / s;

    float a0 = 0.f, a1 = 0.f;
#pragma unroll
    for (int f = 0; f < 25; f++) {
        const int ny = y + f / 5 - 2;
        const int nx = x + f % 5 - 2;
        if ((unsigned)ny < (unsigned)HMAPC && (unsigned)nx < (unsigned)WMAPC) {
            const float* vp = base + (size_t)((ny << 6) + nx) * QKV_N
                              + 2 * INNER + head * HD;
            const float wf = dots[f] * inv;
            a0 += wf * vp[lane];
            a1 += wf * vp[lane + 32];
        }
    }

    float* op = out + (size_t)(b * NPIX + pix) * INNER + head * HD;
    op[lane]      = a0;
    op[lane + 32] = a1;
}

// ---------------------------------------------------------------------------
// Launch
// ---------------------------------------------------------------------------
extern "C" void kernel_launch(void* const* d_in, const int* in_sizes, int n_in,
                              void* d_out, int out_size)
{
    const float* x     = (const float*)d_in[0];
    const float* w_qkv = (const float*)d_in[1];
    const float* w_out = (const float*)d_in[2];
    const float* b_out = (const float*)d_in[3];
    float* out = (float*)d_out;

    float* qkv = nullptr;
    float* att = nullptr;
    cudaGetSymbolAddress((void**)&qkv, g_qkv);
    cudaGetSymbolAddress((void**)&att, g_att);

    // GEMM1: qkv = x @ w_qkv^T   [16384,512] x [1536,512]^T -> [16384,1536]
    dim3 g1(QKV_N / BN, MROWS / BM);
    gemm_tn<<<g1, 256>>>(x, w_qkv, nullptr, qkv, MROWS, QKV_N, DIMM);

    // Local attention -> [16384, 512]
    local_attn<<<(Bq * HEADS * NPIX) / 8, 256>>>(qkv, att);

    // GEMM2: out = att @ w_out^T + b_out   [16384,512] x [512,512]^T
    dim3 g2(DIMM / BN, MROWS / BM);
    gemm_tn<<<g2, 256>>>(att, w_out, b_out, out, MROWS, DIMM, INNER);
}

// round 3
// speedup vs baseline: 1.1006x; 1.1006x over previous
#include <cuda_runtime.h>
#include <cuda_bf16.h>
#include <cstdint>

// Problem constants (fixed by reference setup_inputs)
#define Bq     4
#define NPIX   4096          // 64*64
#define HEADS  8
#define HD     64
#define DIMM   512
#define INNER  512           // HEADS*HD
#define MROWS  (Bq*NPIX)     // 16384
#define QKV_N  (3*INNER)     // 1536

// Scratch (device globals — no runtime allocation allowed)
__device__ float g_qkv[(size_t)MROWS * QKV_N];   // ~100.7 MB
__device__ float g_att[(size_t)MROWS * INNER];   // ~33.5 MB

// ---------------------------------------------------------------------------
// Packed fp32x2 helpers (sm_103a FFMA2 — only reachable via PTX fma.rn.f32x2)
// ---------------------------------------------------------------------------
__device__ __forceinline__ unsigned long long fma_f32x2(unsigned long long a,
                                                        unsigned long long b,
                                                        unsigned long long c) {
    unsigned long long d;
    asm("fma.rn.f32x2 %0, %1, %2, %3;" : "=l"(d) : "l"(a), "l"(b), "l"(c));
    return d;
}
__device__ __forceinline__ unsigned long long pack2(float x) {
    unsigned long long r;
    asm("mov.b64 %0, {%1, %1};" : "=l"(r) : "f"(x));
    return r;
}
__device__ __forceinline__ unsigned long long packab(float a, float b) {
    unsigned long long r;
    asm("mov.b64 %0, {%1, %2};" : "=l"(r) : "f"(a), "f"(b));
    return r;
}
__device__ __forceinline__ float lo64(unsigned long long v) {
    return __uint_as_float((unsigned)(v & 0xffffffffull));
}
__device__ __forceinline__ float hi64(unsigned long long v) {
    return __uint_as_float((unsigned)(v >> 32));
}

// ---------------------------------------------------------------------------
// GEMM: C[M,N] = A[M,K] @ B[N,K]^T (+ bias[N]).  Both operands K-major.
// 128x128 tile, BK=8, 256 threads, 8x8 microtile, FFMA2 inner loop,
// register-prefetch software pipeline to hide global-load latency.
// Requires M%128==0, N%128==0, K%8==0.
// ---------------------------------------------------------------------------
#define BM  128
#define BN  128
#define BKK 8
#define TM  8
#define TN  8

__global__ void __launch_bounds__(256, 2)
gemm_tn(const float* __restrict__ A, const float* __restrict__ B,
        const float* __restrict__ bias, float* __restrict__ C,
        int M, int N, int K)
{
    __shared__ float As[BKK][BM];
    __shared__ float Bs[BKK][BN];

    const int tid = threadIdx.x;
    const int tx  = tid & 15;      // N direction, 0..15
    const int ty  = tid >> 4;      // M direction, 0..15
    const int bm  = blockIdx.y * BM;
    const int bn  = blockIdx.x * BN;

    const int lrow = tid >> 1;        // 0..127
    const int lc4  = (tid & 1) * 4;   // 0 or 4

    const float* aptr = &A[(size_t)(bm + lrow) * K + lc4];
    const float* bptr = &B[(size_t)(bn + lrow) * K + lc4];

    unsigned long long acc[TM][TN/2];
#pragma unroll
    for (int i = 0; i < TM; i++)
#pragma unroll
        for (int j = 0; j < TN/2; j++) acc[i][j] = 0ull;

    // prologue prefetch (k0 = 0)
    float4 pa = *reinterpret_cast<const float4*>(aptr);
    float4 pb = *reinterpret_cast<const float4*>(bptr);

    for (int k0 = 0; k0 < K; k0 += BKK) {
        // stage prefetched tile into smem
        As[lc4 + 0][lrow] = pa.x;
        As[lc4 + 1][lrow] = pa.y;
        As[lc4 + 2][lrow] = pa.z;
        As[lc4 + 3][lrow] = pa.w;
        Bs[lc4 + 0][lrow] = pb.x;
        Bs[lc4 + 1][lrow] = pb.y;
        Bs[lc4 + 2][lrow] = pb.z;
        Bs[lc4 + 3][lrow] = pb.w;
        __syncthreads();

        // issue next tile's global loads; latency hides behind compute below
        if (k0 + BKK < K) {
            pa = *reinterpret_cast<const float4*>(aptr + k0 + BKK);
            pb = *reinterpret_cast<const float4*>(bptr + k0 + BKK);
        }

#pragma unroll
        for (int kk = 0; kk < BKK; kk++) {
            float4 a0 = *reinterpret_cast<const float4*>(&As[kk][ty * TM]);
            float4 a1 = *reinterpret_cast<const float4*>(&As[kk][ty * TM + 4]);
            const unsigned long long* bp =
                reinterpret_cast<const unsigned long long*>(&Bs[kk][tx * TN]);
            unsigned long long bb[4];
#pragma unroll
            for (int j = 0; j < 4; j++) bb[j] = bp[j];
            float av[8] = {a0.x, a0.y, a0.z, a0.w, a1.x, a1.y, a1.z, a1.w};
#pragma unroll
            for (int i = 0; i < TM; i++) {
                unsigned long long a2 = pack2(av[i]);
#pragma unroll
                for (int j = 0; j < 4; j++)
                    acc[i][j] = fma_f32x2(a2, bb[j], acc[i][j]);
            }
        }
        __syncthreads();
    }

    // Epilogue
#pragma unroll
    for (int i = 0; i < TM; i++) {
        const int row = bm + ty * TM + i;
        float* cp = &C[(size_t)row * N + bn + tx * TN];
#pragma unroll
        for (int j = 0; j < 4; j++) {
            float lo = lo64(acc[i][j]);
            float hi = hi64(acc[i][j]);
            const int n0 = bn + tx * TN + j * 2;
            if (bias) { lo += bias[n0]; hi += bias[n0 + 1]; }
            *reinterpret_cast<float2*>(&cp[j * 2]) = make_float2(lo, hi);
        }
    }
}

// ---------------------------------------------------------------------------
// Local 5x5 attention. One warp per (b, pixel), ALL 8 heads per warp.
// Lane l owns dims [16l, 16l+16) of the 512-wide inner row; head(l) = l>>2.
// qkv row layout: q[0:512], k[512:1024], v[1024:1536].
// OOB neighbors: k zero-padded -> dot = 0 (participates in softmax), v = 0.
// ---------------------------------------------------------------------------
__global__ void __launch_bounds__(256)
local_attn(const float* __restrict__ qkv, float* __restrict__ out)
{
    const int warp = (blockIdx.x << 3) + (threadIdx.x >> 5);   // 0..16383
    const int lane = threadIdx.x & 31;

    const int pix = warp & (NPIX - 1);
    const int b   = warp >> 12;
    const int y   = pix >> 6;
    const int x   = pix & 63;

    const float* base = qkv + (size_t)b * NPIX * QKV_N;
    const float* qrow = base + (size_t)pix * QKV_N + 16 * lane;

    float4 q4[4];
#pragma unroll
    for (int i = 0; i < 4; i++)
        q4[i] = reinterpret_cast<const float4*>(qrow)[i];

    float dots[25];
#pragma unroll
    for (int f = 0; f < 25; f++) {
        const int ny = y + f / 5 - 2;
        const int nx = x + f % 5 - 2;
        float d = 0.f;
        if ((unsigned)ny < 64u && (unsigned)nx < 64u) {
            const float4* kp = reinterpret_cast<const float4*>(
                base + (size_t)((ny << 6) + nx) * QKV_N + INNER + 16 * lane);
            unsigned long long p2 = 0ull;
#pragma unroll
            for (int i = 0; i < 4; i++) {
                float4 k4 = kp[i];
                p2 = fma_f32x2(packab(q4[i].x, q4[i].y),
                               packab(k4.x, k4.y), p2);
                p2 = fma_f32x2(packab(q4[i].z, q4[i].w),
                               packab(k4.z, k4.w), p2);
            }
            d = lo64(p2) + hi64(p2);
        }
        // reduce over the 4 lanes sharing this head
        d += __shfl_xor_sync(0xffffffffu, d, 1);
        d += __shfl_xor_sync(0xffffffffu, d, 2);
        dots[f] = d * 0.125f;   // 64^-0.5
    }

    float m = dots[0];
#pragma unroll
    for (int f = 1; f < 25; f++) m = fmaxf(m, dots[f]);
    float s = 0.f;
#pragma unroll
    for (int f = 0; f < 25; f++) { dots[f] = __expf(dots[f] - m); s += dots[f]; }
    const float inv = 1.0f / s;

    unsigned long long acc[8];
#pragma unroll
    for (int i = 0; i < 8; i++) acc[i] = 0ull;

#pragma unroll
    for (int f = 0; f < 25; f++) {
        const int ny = y + f / 5 - 2;
        const int nx = x + f % 5 - 2;
        if ((unsigned)ny < 64u && (unsigned)nx < 64u) {
            const float4* vp = reinterpret_cast<const float4*>(
                base + (size_t)((ny << 6) + nx) * QKV_N + 2 * INNER + 16 * lane);
            const unsigned long long w2 = pack2(dots[f] * inv);
#pragma unroll
            for (int i = 0; i < 4; i++) {
                float4 v4 = vp[i];
                acc[2 * i]     = fma_f32x2(w2, packab(v4.x, v4.y), acc[2 * i]);
                acc[2 * i + 1] = fma_f32x2(w2, packab(v4.z, v4.w), acc[2 * i + 1]);
            }
        }
    }

    float* op = out + (size_t)(b * NPIX + pix) * INNER + 16 * lane;
#pragma unroll
    for (int i = 0; i < 4; i++) {
        float4 v4 = make_float4(lo64(acc[2 * i]), hi64(acc[2 * i]),
                                lo64(acc[2 * i + 1]), hi64(acc[2 * i + 1]));
        reinterpret_cast<float4*>(op)[i] = v4;
    }
}

// ---------------------------------------------------------------------------
// Launch
// ---------------------------------------------------------------------------
extern "C" void kernel_launch(void* const* d_in, const int* in_sizes, int n_in,
                              void* d_out, int out_size)
{
    const float* x     = (const float*)d_in[0];
    const float* w_qkv = (const float*)d_in[1];
    const float* w_out = (const float*)d_in[2];
    const float* b_out = (const float*)d_in[3];
    float* out = (float*)d_out;

    float* qkv = nullptr;
    float* att = nullptr;
    cudaGetSymbolAddress((void**)&qkv, g_qkv);
    cudaGetSymbolAddress((void**)&att, g_att);

    // GEMM1: qkv = x @ w_qkv^T   [16384,512] x [1536,512]^T -> [16384,1536]
    dim3 g1(QKV_N / BN, MROWS / BM);
    gemm_tn<<<g1, 256>>>(x, w_qkv, nullptr, qkv, MROWS, QKV_N, DIMM);

    // Local attention -> [16384, 512]
    local_attn<<<(Bq * NPIX) / 8, 256>>>(qkv, att);

    // GEMM2: out = att @ w_out^T + b_out   [16384,512] x [512,512]^T
    dim3 g2(DIMM / BN, MROWS / BM);
    gemm_tn<<<g2, 256>>>(att, w_out, b_out, out, MROWS, DIMM, INNER);
}

// round 7
// speedup vs baseline: 2.3128x; 2.1015x over previous
#include <cuda_runtime.h>
#include <cuda_bf16.h>
#include <cstdint>

// Problem constants (fixed by reference setup_inputs)
#define Bq     4
#define NPIX   4096          // 64*64
#define HEADS  8
#define HD     64
#define DIMM   512
#define INNER  512           // HEADS*HD
#define MROWS  (Bq*NPIX)     // 16384
#define QKV_N  (3*INNER)     // 1536

// Scratch (device globals — no runtime allocation allowed)
__device__ float g_qkv[(size_t)MROWS * QKV_N];   // ~100.7 MB
__device__ float g_att[(size_t)MROWS * INNER];   // ~33.5 MB

// ---------------------------------------------------------------------------
// Packed fp32x2 helpers (attention kernel)
// ---------------------------------------------------------------------------
__device__ __forceinline__ unsigned long long fma_f32x2(unsigned long long a,
                                                        unsigned long long b,
                                                        unsigned long long c) {
    unsigned long long d;
    asm("fma.rn.f32x2 %0, %1, %2, %3;" : "=l"(d) : "l"(a), "l"(b), "l"(c));
    return d;
}
__device__ __forceinline__ unsigned long long pack2(float x) {
    unsigned long long r;
    asm("mov.b64 %0, {%1, %1};" : "=l"(r) : "f"(x));
    return r;
}
__device__ __forceinline__ unsigned long long packab(float a, float b) {
    unsigned long long r;
    asm("mov.b64 %0, {%1, %2};" : "=l"(r) : "f"(a), "f"(b));
    return r;
}
__device__ __forceinline__ float lo64(unsigned long long v) {
    return __uint_as_float((unsigned)(v & 0xffffffffull));
}
__device__ __forceinline__ float hi64(unsigned long long v) {
    return __uint_as_float((unsigned)(v >> 32));
}

// ---------------------------------------------------------------------------
// Warp-level tensor-core primitives (base PTX — compile at compute_103)
// ---------------------------------------------------------------------------
__device__ __forceinline__ uint32_t smem_u32(const void* p) {
    uint32_t a;
    asm("{ .reg .u64 t; cvta.to.shared.u64 t, %1; cvt.u32.u64 %0, t; }"
        : "=r"(a) : "l"(p));
    return a;
}
__device__ __forceinline__ void ldm_x4(uint32_t* r, uint32_t addr) {
    asm volatile("ldmatrix.sync.aligned.m8n8.x4.shared.b16 {%0,%1,%2,%3}, [%4];"
                 : "=r"(r[0]), "=r"(r[1]), "=r"(r[2]), "=r"(r[3]) : "r"(addr));
}
__device__ __forceinline__ void mma16816(float* d, const uint32_t* a,
                                         uint32_t b0, uint32_t b1) {
    asm volatile(
        "mma.sync.aligned.m16n8k16.row.col.f32.bf16.bf16.f32 "
        "{%0,%1,%2,%3}, {%4,%5,%6,%7}, {%8,%9}, {%0,%1,%2,%3};"
        : "+f"(d[0]), "+f"(d[1]), "+f"(d[2]), "+f"(d[3])
        : "r"(a[0]), "r"(a[1]), "r"(a[2]), "r"(a[3]), "r"(b0), "r"(b1));
}
#define SMEM_SWIZZLE_128B(b) ((b) ^ (((b) >> 3) & 0x70))

// ---------------------------------------------------------------------------
// bf16-split GEMM via mma.sync: C[M,N] = A[M,K] @ B[N,K]^T (+ bias[N]).
// fp32 -> bf16 hi+lo; D = Ah*Bh + Ah*Bl + Al*Bh, fp32 accumulate.
// CTA 128x128, 256 threads (8 warps: 4 M x 2 N, warp tile 32x64), BK=64.
// Smem tiles: 128 rows x 64 bf16 (128B rows), SW128 swizzle, K-major.
// Requires M%128==0, N%128==0, K%64==0.
// ---------------------------------------------------------------------------
#define G_BK     64
#define TILE_B   16384                      // one 128x64 bf16 tile
#define SM_A_HI  0
#define SM_A_LO  16384
#define SM_B_HI  32768
#define SM_B_LO  49152
#define SM_TOTAL 65536

__device__ __forceinline__ void load_split_tile(
    const float* __restrict__ src, int K, int k0,
    char* smem, int off_hi, int off_lo, int tid)
{
    // tile: 128 rows x 64 fp32 cols at src[row*K + k0 + col]
#pragma unroll
    for (int i = 0; i < 4; i++) {
        const int idx = tid + 256 * i;   // 0..1023 chunk id
        const int row = idx >> 3;
        const int cc  = idx & 7;         // 8-elem chunk within row
        const float4* gp = reinterpret_cast<const float4*>(
            src + (size_t)row * K + k0 + cc * 8);
        float4 f0 = gp[0];
        float4 f1 = gp[1];
        float fs[8] = {f0.x, f0.y, f0.z, f0.w, f1.x, f1.y, f1.z, f1.w};
        __nv_bfloat162 hv[4], lv[4];
#pragma unroll
        for (int j = 0; j < 4; j++) {
            const float a = fs[2 * j], b = fs[2 * j + 1];
            const __nv_bfloat16 ha = __float2bfloat16_rn(a);
            const __nv_bfloat16 hb = __float2bfloat16_rn(b);
            hv[j].x = ha; hv[j].y = hb;
            lv[j].x = __float2bfloat16_rn(a - __bfloat162float(ha));
            lv[j].y = __float2bfloat16_rn(b - __bfloat162float(hb));
        }
        const uint32_t sw = SMEM_SWIZZLE_128B((uint32_t)(row * 128 + cc * 16));
        *reinterpret_cast<uint4*>(smem + off_hi + sw) =
            *reinterpret_cast<uint4*>(hv);
        *reinterpret_cast<uint4*>(smem + off_lo + sw) =
            *reinterpret_cast<uint4*>(lv);
    }
}

__global__ void __launch_bounds__(256, 2)
gemm_mma(const float* __restrict__ A, const float* __restrict__ B,
         const float* __restrict__ bias, float* __restrict__ C,
         int M, int N, int K)
{
    extern __shared__ char smem[];
    const uint32_t sbase = smem_u32(smem);
    const int tid  = threadIdx.x;
    const int wid  = tid >> 5;
    const int lane = tid & 31;
    const int wm   = wid & 3;       // 4 warp rows, 32 M each
    const int wn   = wid >> 2;      // 2 warp cols, 64 N each
    const int bn   = blockIdx.x * 128;
    const int bm   = blockIdx.y * 128;

    const float* Ab = A + (size_t)bm * K;
    const float* Bb = B + (size_t)bn * K;

    // Precompute ldmatrix lane addresses (swizzled), K-offset added per kstep.
    // A tiles: m16xk16 at row rA(t) = wm*32 + t*16 + (lane&15),
    //          kb = ks*32 + (lane>>4)*16
    uint32_t aAddr[2], aXor;
    {
        const int rlo = lane & 15;
        const int sub = (lane >> 4) * 16;
#pragma unroll
        for (int t = 0; t < 2; t++) {
            const int row = wm * 32 + t * 16 + rlo;
            aAddr[t] = sbase + SM_A_HI + row * 128
                     + (uint32_t)(sub ^ ((row & 7) << 4));
        }
        aXor = 0;  // kstep offset applied as +ks*32 XOR-free (bits 5-6 clear in stored xor)
        (void)aXor;
    }
    // B tiles: pair of n8 tiles per ldmatrix.x4.
    //   nrow = wn*64 + g*16 + (lane&7) + ((lane&16)>>1)
    //   kb   = ks*32 + ((lane&8)<<1)
    uint32_t bAddr[4];
    {
        const int nlo = (lane & 7) + ((lane & 16) >> 1);
        const int sub = (lane & 8) << 1;
#pragma unroll
        for (int g = 0; g < 4; g++) {
            const int row = wn * 64 + g * 16 + nlo;
            bAddr[g] = sbase + SM_B_HI + row * 128
                     + (uint32_t)(sub ^ ((row & 7) << 4));
        }
    }
    // NOTE: adding ks*32 to these addresses is correct because the stored
    // offset's bits 5-6 come only from `sub^((row&7)<<4)`: sub occupies bit 4
    // (A) or bit 5 (B) ... to be safe we recompute the XOR per kstep below.

    float acc[2][8][4];
#pragma unroll
    for (int t = 0; t < 2; t++)
#pragma unroll
        for (int n = 0; n < 8; n++)
#pragma unroll
            for (int j = 0; j < 4; j++) acc[t][n][j] = 0.f;

    const int NC = K / G_BK;
    for (int c = 0; c < NC; c++) {
        load_split_tile(Ab, K, c * G_BK, smem, SM_A_HI, SM_A_LO, tid);
        load_split_tile(Bb, K, c * G_BK, smem, SM_B_HI, SM_B_LO, tid);
        __syncthreads();

#pragma unroll
        for (int ks = 0; ks < 4; ks++) {
            // XOR-correct kstep offset: kb bits live in [4:6]; the stored
            // address already XORed sub with (row&7)<<4. Adding ks*32 must go
            // through the same XOR. Since (a ^ m) with m in bits[4:6] and
            // adding ks*32 (bits[5:6]) can carry across XORed bits, recompute:
            // addr_ks = base_row + ((sub + ks*32) ^ mask). We exploit that
            // sub + ks*32 never carries past bit 6 (max 16+96=112) and mask
            // bits are XORed, so addr_ks = (addr - (sub^mask)) + ((sub+ks*32)^mask).
            // To keep it simple we precomputed addr with sub^mask included and
            // note (sub + ks*32) ^ mask = (sub ^ mask) + ks*32 only when
            // ks*32 bits don't collide with mask bits 5-6 — they do. So:
            // use XOR trick: ks*32 toggles bits 5-6; (x ^ k32) == x + k32 when
            // those bits of x are clear — not guaranteed. Hence full recompute
            // below (cheap ALU, hidden under tensor ops).
            uint32_t a0 = aAddr[0], a1 = aAddr[1];
            uint32_t b0 = bAddr[0], b1 = bAddr[1], b2 = bAddr[2], b3 = bAddr[3];
            {
                // subtract stored (sub^mask), add ((sub + ks*32)^mask)
                const int subA = (lane >> 4) * 16;
                const int subB = (lane & 8) << 1;
                const int kso  = ks * 32;
#pragma unroll
                for (int t = 0; t < 2; t++) {
                    const int row = wm * 32 + t * 16 + (lane & 15);
                    const uint32_t mask = (row & 7) << 4;
                    const uint32_t adj = ((uint32_t)(subA + kso) ^ mask)
                                       - ((uint32_t)subA ^ mask);
                    if (t == 0) a0 += adj; else a1 += adj;
                }
                const int nlo = (lane & 7) + ((lane & 16) >> 1);
#pragma unroll
                for (int g = 0; g < 4; g++) {
                    const int row = wn * 64 + g * 16 + nlo;
                    const uint32_t mask = (row & 7) << 4;
                    const uint32_t adj = ((uint32_t)(subB + kso) ^ mask)
                                       - ((uint32_t)subB ^ mask);
                    if (g == 0) b0 += adj;
                    else if (g == 1) b1 += adj;
                    else if (g == 2) b2 += adj;
                    else b3 += adj;
                }
            }

            uint32_t Ah[2][4], Al[2][4];
            ldm_x4(Ah[0], a0);
            ldm_x4(Ah[1], a1);
            ldm_x4(Al[0], a0 + TILE_B);
            ldm_x4(Al[1], a1 + TILE_B);

            const uint32_t bA[4] = {b0, b1, b2, b3};
#pragma unroll
            for (int g = 0; g < 4; g++) {
                uint32_t Bh[4], Bl[4];
                ldm_x4(Bh, bA[g]);
                ldm_x4(Bl, bA[g] + TILE_B);
#pragma unroll
                for (int half = 0; half < 2; half++) {
                    const int n = g * 2 + half;
                    const uint32_t bh0 = Bh[half * 2], bh1 = Bh[half * 2 + 1];
                    const uint32_t bl0 = Bl[half * 2], bl1 = Bl[half * 2 + 1];
#pragma unroll
                    for (int t = 0; t < 2; t++) {
                        mma16816(acc[t][n], Ah[t], bh0, bh1);
                        mma16816(acc[t][n], Ah[t], bl0, bl1);
                        mma16816(acc[t][n], Al[t], bh0, bh1);
                    }
                }
            }
        }
        __syncthreads();
    }

    // Epilogue: fragment (t,n): rows bm+wm*32+t*16+lane/4 (+8),
    // cols bn+wn*64+n*8+(lane&3)*2.
    const int crow = bm + wm * 32 + (lane >> 2);
    const int ccol = bn + wn * 64 + (lane & 3) * 2;
#pragma unroll
    for (int t = 0; t < 2; t++) {
        const int r0 = crow + t * 16;
#pragma unroll
        for (int n = 0; n < 8; n++) {
            const int col = ccol + n * 8;
            float bx = 0.f, by = 0.f;
            if (bias) { bx = __ldg(bias + col); by = __ldg(bias + col + 1); }
            *reinterpret_cast<float2*>(&C[(size_t)r0 * N + col]) =
                make_float2(acc[t][n][0] + bx, acc[t][n][1] + by);
            *reinterpret_cast<float2*>(&C[(size_t)(r0 + 8) * N + col]) =
                make_float2(acc[t][n][2] + bx, acc[t][n][3] + by);
        }
    }
}

// ---------------------------------------------------------------------------
// Local 5x5 attention. One warp per (b, pixel), ALL 8 heads per warp.
// Lane l owns dims [16l, 16l+16); head(l) = l>>2.
// qkv row layout: q[0:512], k[512:1024], v[1024:1536].
// OOB neighbors: dot = 0 (participates in softmax), v = 0.
// ---------------------------------------------------------------------------
__global__ void __launch_bounds__(256)
local_attn(const float* __restrict__ qkv, float* __restrict__ out)
{
    const int warp = (blockIdx.x << 3) + (threadIdx.x >> 5);   // 0..16383
    const int lane = threadIdx.x & 31;

    const int pix = warp & (NPIX - 1);
    const int b   = warp >> 12;
    const int y   = pix >> 6;
    const int x   = pix & 63;

    const float* base = qkv + (size_t)b * NPIX * QKV_N;
    const float* qrow = base + (size_t)pix * QKV_N + 16 * lane;

    float4 q4[4];
#pragma unroll
    for (int i = 0; i < 4; i++)
        q4[i] = reinterpret_cast<const float4*>(qrow)[i];

    float dots[25];
#pragma unroll
    for (int f = 0; f < 25; f++) {
        const int ny = y + f / 5 - 2;
        const int nx = x + f % 5 - 2;
        float d = 0.f;
        if ((unsigned)ny < 64u && (unsigned)nx < 64u) {
            const float4* kp = reinterpret_cast<const float4*>(
                base + (size_t)((ny << 6) + nx) * QKV_N + INNER + 16 * lane);
            unsigned long long p2 = 0ull;
#pragma unroll
            for (int i = 0; i < 4; i++) {
                float4 k4 = kp[i];
                p2 = fma_f32x2(packab(q4[i].x, q4[i].y),
                               packab(k4.x, k4.y), p2);
                p2 = fma_f32x2(packab(q4[i].z, q4[i].w),
                               packab(k4.z, k4.w), p2);
            }
            d = lo64(p2) + hi64(p2);
        }
        d += __shfl_xor_sync(0xffffffffu, d, 1);
        d += __shfl_xor_sync(0xffffffffu, d, 2);
        dots[f] = d * 0.125f;   // 64^-0.5
    }

    float m = dots[0];
#pragma unroll
    for (int f = 1; f < 25; f++) m = fmaxf(m, dots[f]);
    float s = 0.f;
#pragma unroll
    for (int f = 0; f < 25; f++) { dots[f] = __expf(dots[f] - m); s += dots[f]; }
    const float inv = 1.0f / s;

    unsigned long long acc[8];
#pragma unroll
    for (int i = 0; i < 8; i++) acc[i] = 0ull;

#pragma unroll
    for (int f = 0; f < 25; f++) {
        const int ny = y + f / 5 - 2;
        const int nx = x + f % 5 - 2;
        if ((unsigned)ny < 64u && (unsigned)nx < 64u) {
            const float4* vp = reinterpret_cast<const float4*>(
                base + (size_t)((ny << 6) + nx) * QKV_N + 2 * INNER + 16 * lane);
            const unsigned long long w2 = pack2(dots[f] * inv);
#pragma unroll
            for (int i = 0; i < 4; i++) {
                float4 v4 = vp[i];
                acc[2 * i]     = fma_f32x2(w2, packab(v4.x, v4.y), acc[2 * i]);
                acc[2 * i + 1] = fma_f32x2(w2, packab(v4.z, v4.w), acc[2 * i + 1]);
            }
        }
    }

    float* op = out + (size_t)(b * NPIX + pix) * INNER + 16 * lane;
#pragma unroll
    for (int i = 0; i < 4; i++) {
        float4 v4 = make_float4(lo64(acc[2 * i]), hi64(acc[2 * i]),
                                lo64(acc[2 * i + 1]), hi64(acc[2 * i + 1]));
        reinterpret_cast<float4*>(op)[i] = v4;
    }
}

// ---------------------------------------------------------------------------
// Launch
// ---------------------------------------------------------------------------
extern "C" void kernel_launch(void* const* d_in, const int* in_sizes, int n_in,
                              void* d_out, int out_size)
{
    const float* x     = (const float*)d_in[0];
    const float* w_qkv = (const float*)d_in[1];
    const float* w_out = (const float*)d_in[2];
    const float* b_out = (const float*)d_in[3];
    float* out = (float*)d_out;

    float* qkv = nullptr;
    float* att = nullptr;
    cudaGetSymbolAddress((void**)&qkv, g_qkv);
    cudaGetSymbolAddress((void**)&att, g_att);

    cudaFuncSetAttribute(gemm_mma,
                         cudaFuncAttributeMaxDynamicSharedMemorySize, SM_TOTAL);

    // GEMM1: qkv = x @ w_qkv^T   [16384,512] x [1536,512]^T -> [16384,1536]
    dim3 g1(QKV_N / 128, MROWS / 128);
    gemm_mma<<<g1, 256, SM_TOTAL>>>(x, w_qkv, nullptr, qkv, MROWS, QKV_N, DIMM);

    // Local attention -> [16384, 512]
    local_attn<<<(Bq * NPIX) / 8, 256>>>(qkv, att);

    // GEMM2: out = att @ w_out^T + b_out   [16384,512] x [512,512]^T
    dim3 g2(DIMM / 128, MROWS / 128);
    gemm_mma<<<g2, 256, SM_TOTAL>>>(att, w_out, b_out, out, MROWS, DIMM, INNER);
}